// round 5
// baseline (speedup 1.0000x reference)
#include <cuda_runtime.h>

#define NN 20000
#define EE 320000
#define ETOT (EE + NN)
#define C1 256
#define C2 128
#define H1 4
#define NEG 0.2f
#define BN_EPS 1e-5f
#define SCANB ((NN + 255) / 256)   /* 79 */

// ---------------- scratch ----------------
__device__ __align__(16) float g_h1[NN * C1];
__device__ __align__(16) float g_b1[NN * C1];
__device__ __align__(16) float g_h2[NN * C2];
__device__ __align__(16) float g_b2[NN * C2];
__device__ __align__(16) float g_as1[NN * H1];
__device__ __align__(16) float g_ad1[NN * H1];
__device__ __align__(16) float g_e1[(size_t)ETOT * H1];   // edge-order logits L1
__device__ __align__(16) float g_e1o[(size_t)ETOT * H1];  // CSR-order exp'd logits L1
__device__ float g_e2o[ETOT];                              // CSR-order logits L2
__device__ int   g_max1[NN * H1];
__device__ float g_as2[NN], g_ad2[NN];
__device__ int   g_max2[NN];
__device__ int   g_src[ETOT], g_dst[ETOT];
__device__ int   g_srco[ETOT], g_dsto[ETOT];
__device__ int   g_cnt[NN], g_cur[NN];
__device__ int   g_off[NN + 1];
__device__ int   g_bsum[SCANB], g_boff[SCANB];
__device__ float g_sum[C1], g_sq[C1];
__device__ int   g_is64;

// ---------------- helpers ----------------
__device__ __forceinline__ int f2ord(float f) {
    int i = __float_as_int(f);
    return i >= 0 ? i : i ^ 0x7FFFFFFF;
}
__device__ __forceinline__ float ord2f(int i) {
    return __int_as_float(i >= 0 ? i : i ^ 0x7FFFFFFF);
}
__device__ __forceinline__ float lrelu(float v) { return v > 0.f ? v : NEG * v; }

__global__ void k_detect(const unsigned* __restrict__ p) {
    int all0 = 1;
    for (int i = 0; i < 64; i++) all0 &= (p[2 * i + 1] == 0u);
    g_is64 = all0;
}

// ---------------- SGEMM: 128x64 tile, 8x4 per thread, reg prefetch ----------------
__device__ __forceinline__ void sgemm128x64(const float* __restrict__ A,
                                            const float* __restrict__ B,
                                            float* __restrict__ C,
                                            int M, int N, int K) {
    const int BK = 16;
    __shared__ float As[BK][128];
    __shared__ float Bs[BK][64];
    int tid = threadIdx.x;              // 256
    int tx = tid & 15, ty = tid >> 4;
    int row0 = blockIdx.y * 128, col0 = blockIdx.x * 64;
    int ntiles = K / BK;
    float4 pa[2], pb;
#pragma unroll
    for (int l = 0; l < 2; l++) {
        int s = tid + l * 256;
        int ar = s >> 2, ak = (s & 3) << 2;
        int r = row0 + ar;
        pa[l] = (r < M) ? *(const float4*)(A + (size_t)r * K + ak)
                        : make_float4(0.f, 0.f, 0.f, 0.f);
    }
    {
        int bk = tid >> 4, bn = (tid & 15) << 2;
        pb = *(const float4*)(B + (size_t)bk * N + col0 + bn);
    }
    float acc[8][4] = {};
    for (int kt = 0; kt < ntiles; kt++) {
        __syncthreads();
#pragma unroll
        for (int l = 0; l < 2; l++) {
            int s = tid + l * 256;
            int ar = s >> 2, ak = (s & 3) << 2;
            As[ak + 0][ar] = pa[l].x;
            As[ak + 1][ar] = pa[l].y;
            As[ak + 2][ar] = pa[l].z;
            As[ak + 3][ar] = pa[l].w;
        }
        {
            int bk = tid >> 4, bn = (tid & 15) << 2;
            *(float4*)&Bs[bk][bn] = pb;
        }
        __syncthreads();
        if (kt + 1 < ntiles) {
            int k0 = (kt + 1) * BK;
#pragma unroll
            for (int l = 0; l < 2; l++) {
                int s = tid + l * 256;
                int ar = s >> 2, ak = (s & 3) << 2;
                int r = row0 + ar;
                pa[l] = (r < M) ? *(const float4*)(A + (size_t)r * K + k0 + ak)
                                : make_float4(0.f, 0.f, 0.f, 0.f);
            }
            int bk = tid >> 4, bn = (tid & 15) << 2;
            pb = *(const float4*)(B + (size_t)(k0 + bk) * N + col0 + bn);
        }
#pragma unroll
        for (int k = 0; k < BK; k++) {
            float4 a0 = *(float4*)&As[k][ty * 8];
            float4 a1 = *(float4*)&As[k][ty * 8 + 4];
            float4 b0 = *(float4*)&Bs[k][tx * 4];
            float av[8] = {a0.x, a0.y, a0.z, a0.w, a1.x, a1.y, a1.z, a1.w};
            float bv[4] = {b0.x, b0.y, b0.z, b0.w};
#pragma unroll
            for (int i = 0; i < 8; i++)
#pragma unroll
                for (int j = 0; j < 4; j++) acc[i][j] += av[i] * bv[j];
        }
    }
#pragma unroll
    for (int i = 0; i < 8; i++) {
        int r = row0 + ty * 8 + i;
        if (r >= M) continue;
        *(float4*)(C + (size_t)r * N + col0 + tx * 4) =
            make_float4(acc[i][0], acc[i][1], acc[i][2], acc[i][3]);
    }
}

__global__ void __launch_bounds__(256) k_gemm1(const float* __restrict__ x,
                                               const float* __restrict__ W1) {
    sgemm128x64(x, W1, g_h1, NN, C1, 128);
}
__global__ void __launch_bounds__(256) k_gemm2(const float* __restrict__ W2) {
    sgemm128x64(g_b1, W2, g_h2, NN, C2, C1);
}

// ---------------- per-node alpha projections ----------------
__global__ void k_alphas1(const float* __restrict__ attS, const float* __restrict__ attD) {
    int idx = blockIdx.x * blockDim.x + threadIdx.x;
    if (idx < NN) g_cnt[idx] = 0;
    if (idx < C1) { g_sum[idx] = 0.f; g_sq[idx] = 0.f; }
    if (idx >= NN * H1) return;
    int n = idx >> 2, h = idx & 3;
    const float4* hp = (const float4*)(g_h1 + (size_t)n * C1 + h * 64);
    const float4* ap = (const float4*)(attS + h * 64);
    const float4* bp = (const float4*)(attD + h * 64);
    float s = 0.f, d = 0.f;
#pragma unroll
    for (int i = 0; i < 16; i++) {
        float4 hv = hp[i], a = ap[i], b = bp[i];
        s += hv.x * a.x + hv.y * a.y + hv.z * a.z + hv.w * a.w;
        d += hv.x * b.x + hv.y * b.y + hv.z * b.z + hv.w * b.w;
    }
    g_as1[idx] = s;
    g_ad1[idx] = d;
    g_max1[idx] = (int)0x80000000;
}

__global__ void k_alphas2(const float* __restrict__ attS, const float* __restrict__ attD) {
    int n = blockIdx.x * blockDim.x + threadIdx.x;
    if (n < C1) { g_sum[n] = 0.f; g_sq[n] = 0.f; }
    if (n >= NN) return;
    const float4* hp = (const float4*)(g_h2 + (size_t)n * C2);
    const float4* ap = (const float4*)attS;
    const float4* bp = (const float4*)attD;
    float s = 0.f, d = 0.f;
#pragma unroll
    for (int i = 0; i < 32; i++) {
        float4 hv = hp[i], a = ap[i], b = bp[i];
        s += hv.x * a.x + hv.y * a.y + hv.z * a.z + hv.w * a.w;
        d += hv.x * b.x + hv.y * b.y + hv.z * b.z + hv.w * b.w;
    }
    g_as2[n] = s;
    g_ad2[n] = d;
    g_max2[n] = (int)0x80000000;
}

// ---------------- edge pass 1, layer 1: logits + max + count ----------------
__global__ void k_pass1_l1(const void* __restrict__ ei) {
    int e = blockIdx.x * blockDim.x + threadIdx.x;
    if (e >= ETOT) return;
    int s, d;
    if (e < EE) {
        if (g_is64) {
            s = (int)((const long long*)ei)[e];
            d = (int)((const long long*)ei)[EE + e];
        } else {
            s = ((const int*)ei)[e];
            d = ((const int*)ei)[EE + e];
        }
    } else {
        s = d = e - EE;
    }
    g_src[e] = s;
    g_dst[e] = d;
    atomicAdd(&g_cnt[d], 1);
    float4 a = *(const float4*)(g_as1 + s * 4);
    float4 b = *(const float4*)(g_ad1 + d * 4);
    float4 v;
    v.x = lrelu(a.x + b.x);
    v.y = lrelu(a.y + b.y);
    v.z = lrelu(a.z + b.z);
    v.w = lrelu(a.w + b.w);
    *(float4*)(g_e1 + (size_t)e * 4) = v;
    atomicMax(&g_max1[d * 4 + 0], f2ord(v.x));
    atomicMax(&g_max1[d * 4 + 1], f2ord(v.y));
    atomicMax(&g_max1[d * 4 + 2], f2ord(v.z));
    atomicMax(&g_max1[d * 4 + 3], f2ord(v.w));
}

// ---------------- multi-block scan (3 phases) ----------------
__device__ __forceinline__ int block_incl_scan(int v, int* warpsum) {
    int t = threadIdx.x, lane = t & 31, w = t >> 5;
    int incl = v;
#pragma unroll
    for (int o = 1; o < 32; o <<= 1) {
        int u = __shfl_up_sync(~0u, incl, o);
        if (lane >= o) incl += u;
    }
    if (lane == 31) warpsum[w] = incl;
    __syncthreads();
    if (w == 0) {
        int s = (lane < 8) ? warpsum[lane] : 0;
        int is = s;
#pragma unroll
        for (int o = 1; o < 8; o <<= 1) {
            int u = __shfl_up_sync(~0u, is, o);
            if (lane >= o) is += u;
        }
        if (lane < 8) warpsum[lane] = is - s;
    }
    __syncthreads();
    return incl + warpsum[w];
}

__global__ void k_scanA() {
    __shared__ int warpsum[8];
    int i = blockIdx.x * 256 + threadIdx.x;
    int v = (i < NN) ? g_cnt[i] : 0;
    int incl = block_incl_scan(v, warpsum);
    if (i < NN) g_off[i + 1] = incl;
    if (threadIdx.x == 255) g_bsum[blockIdx.x] = incl;
}

__global__ void k_scanB() {
    __shared__ int sh[SCANB];
    int t = threadIdx.x;
    if (t < SCANB) sh[t] = g_bsum[t];
    __syncthreads();
    if (t == 0) {
        int run = 0;
        for (int b = 0; b < SCANB; b++) {
            int v = sh[b];
            g_boff[b] = run;
            run += v;
        }
    }
}

__global__ void k_scanC() {
    int i = blockIdx.x * 256 + threadIdx.x;
    if (i == 0) g_off[0] = 0;
    if (i >= NN) return;
    int incl = g_off[i + 1] + g_boff[blockIdx.x];
    g_off[i + 1] = incl;
    g_cur[i] = incl - g_cnt[i];
}

// ---------------- scatter: exp'd logits + endpoints into CSR order ----------------
__global__ void k_scat1() {
    int e = blockIdx.x * blockDim.x + threadIdx.x;
    if (e >= ETOT) return;
    int s = g_src[e], d = g_dst[e];
    int p = atomicAdd(&g_cur[d], 1);
    float4 v = *(const float4*)(g_e1 + (size_t)e * 4);
    v.x = __expf(v.x - ord2f(g_max1[d * 4 + 0]));
    v.y = __expf(v.y - ord2f(g_max1[d * 4 + 1]));
    v.z = __expf(v.z - ord2f(g_max1[d * 4 + 2]));
    v.w = __expf(v.w - ord2f(g_max1[d * 4 + 3]));
    g_srco[p] = s;
    g_dsto[p] = d;
    *(float4*)(g_e1o + (size_t)p * 4) = v;
}

// ---------------- aggregation L1: contiguous CSR reads, in-block denom ----------------
__global__ void k_agg1() {
    int d = blockIdx.x, tid = threadIdx.x;  // 256
    int head = tid >> 6;
    int lane = tid & 31, w = tid >> 5;
    int beg = g_off[d], end = g_off[d + 1];
    __shared__ int ssrc[128];
    __shared__ __align__(16) float sal[128 * 4];
    __shared__ __align__(16) float4 red[8];
    __shared__ __align__(16) float4 sbc;
    float acc = 0.f;
    float4 den = make_float4(0.f, 0.f, 0.f, 0.f);
    for (int base = beg; base < end; base += 128) {
        int cnt = min(128, end - base);
        __syncthreads();
        for (int i = tid; i < cnt; i += 256) {
            int idx = base + i;
            ssrc[i] = g_srco[idx];
            float4 v = *(const float4*)(g_e1o + (size_t)idx * 4);
            *(float4*)(sal + i * 4) = v;
            den.x += v.x; den.y += v.y; den.z += v.z; den.w += v.w;
        }
        __syncthreads();
        int i = 0;
        for (; i + 4 <= cnt; i += 4) {
            float x0 = g_h1[(size_t)ssrc[i] * C1 + tid];
            float x1 = g_h1[(size_t)ssrc[i + 1] * C1 + tid];
            float x2 = g_h1[(size_t)ssrc[i + 2] * C1 + tid];
            float x3 = g_h1[(size_t)ssrc[i + 3] * C1 + tid];
            acc += x0 * sal[i * 4 + head] + x1 * sal[(i + 1) * 4 + head] +
                   x2 * sal[(i + 2) * 4 + head] + x3 * sal[(i + 3) * 4 + head];
        }
        for (; i < cnt; i++)
            acc += g_h1[(size_t)ssrc[i] * C1 + tid] * sal[i * 4 + head];
    }
    // block-reduce den
#pragma unroll
    for (int o = 16; o; o >>= 1) {
        den.x += __shfl_xor_sync(~0u, den.x, o);
        den.y += __shfl_xor_sync(~0u, den.y, o);
        den.z += __shfl_xor_sync(~0u, den.z, o);
        den.w += __shfl_xor_sync(~0u, den.w, o);
    }
    if (lane == 0) red[w] = den;
    __syncthreads();
    if (tid < 8) {
        float4 v = red[tid];
#pragma unroll
        for (int o = 4; o; o >>= 1) {
            v.x += __shfl_xor_sync(0xff, v.x, o);
            v.y += __shfl_xor_sync(0xff, v.y, o);
            v.z += __shfl_xor_sync(0xff, v.z, o);
            v.w += __shfl_xor_sync(0xff, v.w, o);
        }
        if (tid == 0) sbc = v;
    }
    __syncthreads();
    float4 D = sbc;
    float dh = (head == 0) ? D.x : (head == 1) ? D.y : (head == 2) ? D.z : D.w;
    g_b1[(size_t)d * C1 + tid] = acc / (dh + 1e-16f);
}

// ---------------- layer 2 edge pass: CSR positions, logits + max ----------------
__global__ void k_edge2() {
    int p = blockIdx.x * blockDim.x + threadIdx.x;
    if (p >= ETOT) return;
    int s = g_srco[p], d = g_dsto[p];
    float v = lrelu(g_as2[s] + g_ad2[d]);
    g_e2o[p] = v;
    atomicMax(&g_max2[d], f2ord(v));
}

// ---------------- aggregation L2: exp + denom in-block ----------------
__global__ void k_agg2() {
    int d = blockIdx.x, tid = threadIdx.x;  // 128
    int lane = tid & 31, w = tid >> 5;
    int beg = g_off[d], end = g_off[d + 1];
    __shared__ int ssrc[128];
    __shared__ float sal[128];
    __shared__ float red[4];
    __shared__ float sbc;
    float M = ord2f(g_max2[d]);
    float acc = 0.f, den = 0.f;
    for (int base = beg; base < end; base += 128) {
        int cnt = min(128, end - base);
        __syncthreads();
        for (int i = tid; i < cnt; i += 128) {
            int idx = base + i;
            ssrc[i] = g_srco[idx];
            float v = __expf(g_e2o[idx] - M);
            sal[i] = v;
            den += v;
        }
        __syncthreads();
        int i = 0;
        for (; i + 4 <= cnt; i += 4) {
            acc += g_h2[(size_t)ssrc[i] * C2 + tid] * sal[i] +
                   g_h2[(size_t)ssrc[i + 1] * C2 + tid] * sal[i + 1] +
                   g_h2[(size_t)ssrc[i + 2] * C2 + tid] * sal[i + 2] +
                   g_h2[(size_t)ssrc[i + 3] * C2 + tid] * sal[i + 3];
        }
        for (; i < cnt; i++)
            acc += g_h2[(size_t)ssrc[i] * C2 + tid] * sal[i];
    }
#pragma unroll
    for (int o = 16; o; o >>= 1) den += __shfl_xor_sync(~0u, den, o);
    if (lane == 0) red[w] = den;
    __syncthreads();
    if (tid == 0) sbc = red[0] + red[1] + red[2] + red[3];
    __syncthreads();
    g_b2[(size_t)d * C2 + tid] = acc / (sbc + 1e-16f);
}

// ---------------- BatchNorm ----------------
__global__ void k_bnred1() {
    int c = threadIdx.x;
    int rows = (NN + gridDim.x - 1) / gridDim.x;
    int r0 = blockIdx.x * rows, r1 = min(NN, r0 + rows);
    float s = 0.f, q = 0.f;
    for (int r = r0; r < r1; r++) {
        float v = g_b1[(size_t)r * C1 + c];
        s += v;
        q += v * v;
    }
    atomicAdd(&g_sum[c], s);
    atomicAdd(&g_sq[c], q);
}
__global__ void k_bnred2() {
    int c = threadIdx.x;
    int rows = (NN + gridDim.x - 1) / gridDim.x;
    int r0 = blockIdx.x * rows, r1 = min(NN, r0 + rows);
    float s = 0.f, q = 0.f;
    for (int r = r0; r < r1; r++) {
        float v = g_b2[(size_t)r * C2 + c];
        s += v;
        q += v * v;
    }
    atomicAdd(&g_sum[c], s);
    atomicAdd(&g_sq[c], q);
}

__global__ void k_bnapply1(const float* __restrict__ gamma, const float* __restrict__ beta) {
    int i = blockIdx.x * blockDim.x + threadIdx.x;
    if (i >= NN * C1) return;
    int c = i & (C1 - 1);
    float mean = g_sum[c] * (1.f / NN);
    float var = g_sq[c] * (1.f / NN) - mean * mean;
    float v = (g_b1[i] - mean) * rsqrtf(var + BN_EPS) * gamma[c] + beta[c];
    g_b1[i] = v > 0.f ? v : expm1f(v);
}
__global__ void k_bnapply2(float* __restrict__ out, const float* __restrict__ gamma,
                           const float* __restrict__ beta) {
    int i = blockIdx.x * blockDim.x + threadIdx.x;
    if (i >= NN * C2) return;
    int c = i & (C2 - 1);
    float mean = g_sum[c] * (1.f / NN);
    float var = g_sq[c] * (1.f / NN) - mean * mean;
    out[i] = (g_b2[i] - mean) * rsqrtf(var + BN_EPS) * gamma[c] + beta[c];
}

// ---------------- launch ----------------
extern "C" void kernel_launch(void* const* d_in, const int* in_sizes, int n_in,
                              void* d_out, int out_size) {
    const float* x   = (const float*)d_in[0];
    const void*  ei  = d_in[1];
    const float* W1  = (const float*)d_in[2];
    const float* as1 = (const float*)d_in[3];
    const float* ad1 = (const float*)d_in[4];
    const float* gm1 = (const float*)d_in[6];
    const float* bt1 = (const float*)d_in[7];
    const float* W2  = (const float*)d_in[8];
    const float* as2 = (const float*)d_in[9];
    const float* ad2 = (const float*)d_in[10];
    const float* gm2 = (const float*)d_in[12];
    const float* bt2 = (const float*)d_in[13];
    float* out = (float*)d_out;

    const int EB = (ETOT + 255) / 256;

    k_detect<<<1, 1>>>((const unsigned*)ei);

    // layer 1
    k_gemm1<<<dim3(C1 / 64, (NN + 127) / 128), 256>>>(x, W1);
    k_alphas1<<<(NN * H1 + 255) / 256, 256>>>(as1, ad1);
    k_pass1_l1<<<EB, 256>>>(ei);
    k_scanA<<<SCANB, 256>>>();
    k_scanB<<<1, 128>>>();
    k_scanC<<<SCANB, 256>>>();
    k_scat1<<<EB, 256>>>();
    k_agg1<<<NN, 256>>>();
    k_bnred1<<<148, C1>>>();
    k_bnapply1<<<(NN * C1 + 255) / 256, 256>>>(gm1, bt1);

    // layer 2
    k_gemm2<<<dim3(C2 / 64, (NN + 127) / 128), 256>>>(W2);
    k_alphas2<<<(NN + 255) / 256, 256>>>(as2, ad2);
    k_edge2<<<EB, 256>>>();
    k_agg2<<<NN, 128>>>();
    k_bnred2<<<148, C2>>>();
    k_bnapply2<<<(NN * C2 + 255) / 256, 256>>>(out, gm2, bt2);
}

// round 7
// speedup vs baseline: 1.2521x; 1.2521x over previous
#include <cuda_runtime.h>

#define NN 20000
#define EE 320000
#define ETOT (EE + NN)
#define C1 256
#define C2 128
#define H1 4
#define NEG 0.2f
#define BN_EPS 1e-5f
#define SCANB ((NN + 255) / 256)   /* 79 */

// ---------------- scratch ----------------
__device__ __align__(16) float g_h1[NN * C1];
__device__ __align__(16) float g_b1[NN * C1];
__device__ __align__(16) float g_h2[NN * C2];
__device__ __align__(16) float g_b2[NN * C2];
__device__ __align__(16) float g_as1[NN * H1];
__device__ __align__(16) float g_ad1[NN * H1];
__device__ float g_as2[NN], g_ad2[NN];
__device__ int   g_src[ETOT], g_dst[ETOT];
__device__ int   g_srco[ETOT];
__device__ int   g_cnt[NN], g_cur[NN];
__device__ int   g_off[NN + 1];
__device__ int   g_bsum[SCANB], g_boff[SCANB];
__device__ float g_sum[C1], g_sq[C1];
__device__ int   g_is64;

__device__ __forceinline__ float lrelu(float v) { return v > 0.f ? v : NEG * v; }

__global__ void k_detect(const unsigned* __restrict__ p) {
    int all0 = 1;
    for (int i = 0; i < 64; i++) all0 &= (p[2 * i + 1] == 0u);
    g_is64 = all0;
}

// ---------------- SGEMM: 128x64 tile, 8x4 per thread, reg prefetch ----------------
__device__ __forceinline__ void sgemm128x64(const float* __restrict__ A,
                                            const float* __restrict__ B,
                                            float* __restrict__ C,
                                            int M, int N, int K) {
    const int BK = 16;
    __shared__ float As[BK][128];
    __shared__ float Bs[BK][64];
    int tid = threadIdx.x;              // 256
    int tx = tid & 15, ty = tid >> 4;
    int row0 = blockIdx.y * 128, col0 = blockIdx.x * 64;
    int ntiles = K / BK;
    float4 pa[2], pb;
#pragma unroll
    for (int l = 0; l < 2; l++) {
        int s = tid + l * 256;
        int ar = s >> 2, ak = (s & 3) << 2;
        int r = row0 + ar;
        pa[l] = (r < M) ? *(const float4*)(A + (size_t)r * K + ak)
                        : make_float4(0.f, 0.f, 0.f, 0.f);
    }
    {
        int bk = tid >> 4, bn = (tid & 15) << 2;
        pb = *(const float4*)(B + (size_t)bk * N + col0 + bn);
    }
    float acc[8][4] = {};
    for (int kt = 0; kt < ntiles; kt++) {
        __syncthreads();
#pragma unroll
        for (int l = 0; l < 2; l++) {
            int s = tid + l * 256;
            int ar = s >> 2, ak = (s & 3) << 2;
            As[ak + 0][ar] = pa[l].x;
            As[ak + 1][ar] = pa[l].y;
            As[ak + 2][ar] = pa[l].z;
            As[ak + 3][ar] = pa[l].w;
        }
        {
            int bk = tid >> 4, bn = (tid & 15) << 2;
            *(float4*)&Bs[bk][bn] = pb;
        }
        __syncthreads();
        if (kt + 1 < ntiles) {
            int k0 = (kt + 1) * BK;
#pragma unroll
            for (int l = 0; l < 2; l++) {
                int s = tid + l * 256;
                int ar = s >> 2, ak = (s & 3) << 2;
                int r = row0 + ar;
                pa[l] = (r < M) ? *(const float4*)(A + (size_t)r * K + k0 + ak)
                                : make_float4(0.f, 0.f, 0.f, 0.f);
            }
            int bk = tid >> 4, bn = (tid & 15) << 2;
            pb = *(const float4*)(B + (size_t)(k0 + bk) * N + col0 + bn);
        }
#pragma unroll
        for (int k = 0; k < BK; k++) {
            float4 a0 = *(float4*)&As[k][ty * 8];
            float4 a1 = *(float4*)&As[k][ty * 8 + 4];
            float4 b0 = *(float4*)&Bs[k][tx * 4];
            float av[8] = {a0.x, a0.y, a0.z, a0.w, a1.x, a1.y, a1.z, a1.w};
            float bv[4] = {b0.x, b0.y, b0.z, b0.w};
#pragma unroll
            for (int i = 0; i < 8; i++)
#pragma unroll
                for (int j = 0; j < 4; j++) acc[i][j] += av[i] * bv[j];
        }
    }
#pragma unroll
    for (int i = 0; i < 8; i++) {
        int r = row0 + ty * 8 + i;
        if (r >= M) continue;
        *(float4*)(C + (size_t)r * N + col0 + tx * 4) =
            make_float4(acc[i][0], acc[i][1], acc[i][2], acc[i][3]);
    }
}

__global__ void __launch_bounds__(256) k_gemm1(const float* __restrict__ x,
                                               const float* __restrict__ W1) {
    sgemm128x64(x, W1, g_h1, NN, C1, 128);
}
__global__ void __launch_bounds__(256) k_gemm2(const float* __restrict__ W2) {
    sgemm128x64(g_b1, W2, g_h2, NN, C2, C1);
}

// ---------------- per-node alpha projections (also zeroes counters) ----------------
__global__ void k_alphas1(const float* __restrict__ attS, const float* __restrict__ attD) {
    int idx = blockIdx.x * blockDim.x + threadIdx.x;
    if (idx < NN) g_cnt[idx] = 0;
    if (idx < C1) { g_sum[idx] = 0.f; g_sq[idx] = 0.f; }
    if (idx >= NN * H1) return;
    int n = idx >> 2, h = idx & 3;
    const float4* hp = (const float4*)(g_h1 + (size_t)n * C1 + h * 64);
    const float4* ap = (const float4*)(attS + h * 64);
    const float4* bp = (const float4*)(attD + h * 64);
    float s = 0.f, d = 0.f;
#pragma unroll
    for (int i = 0; i < 16; i++) {
        float4 hv = hp[i], a = ap[i], b = bp[i];
        s += hv.x * a.x + hv.y * a.y + hv.z * a.z + hv.w * a.w;
        d += hv.x * b.x + hv.y * b.y + hv.z * b.z + hv.w * b.w;
    }
    g_as1[idx] = s;
    g_ad1[idx] = d;
}

__global__ void k_alphas2(const float* __restrict__ attS, const float* __restrict__ attD) {
    int n = blockIdx.x * blockDim.x + threadIdx.x;
    if (n < C1) { g_sum[n] = 0.f; g_sq[n] = 0.f; }
    if (n >= NN) return;
    const float4* hp = (const float4*)(g_h2 + (size_t)n * C2);
    const float4* ap = (const float4*)attS;
    const float4* bp = (const float4*)attD;
    float s = 0.f, d = 0.f;
#pragma unroll
    for (int i = 0; i < 32; i++) {
        float4 hv = hp[i], a = ap[i], b = bp[i];
        s += hv.x * a.x + hv.y * a.y + hv.z * a.z + hv.w * a.w;
        d += hv.x * b.x + hv.y * b.y + hv.z * b.z + hv.w * b.w;
    }
    g_as2[n] = s;
    g_ad2[n] = d;
}

// ---------------- edge decode + degree count (AFTER k_alphas1 zeroes g_cnt) ----------------
__global__ void k_count(const void* __restrict__ ei) {
    int e = blockIdx.x * blockDim.x + threadIdx.x;
    if (e >= ETOT) return;
    int s, d;
    if (e < EE) {
        if (g_is64) {
            s = (int)((const long long*)ei)[e];
            d = (int)((const long long*)ei)[EE + e];
        } else {
            s = ((const int*)ei)[e];
            d = ((const int*)ei)[EE + e];
        }
    } else {
        s = d = e - EE;
    }
    g_src[e] = s;
    g_dst[e] = d;
    atomicAdd(&g_cnt[d], 1);
}

// ---------------- multi-block scan (3 phases) ----------------
__device__ __forceinline__ int block_incl_scan(int v, int* warpsum) {
    int t = threadIdx.x, lane = t & 31, w = t >> 5;
    int incl = v;
#pragma unroll
    for (int o = 1; o < 32; o <<= 1) {
        int u = __shfl_up_sync(~0u, incl, o);
        if (lane >= o) incl += u;
    }
    if (lane == 31) warpsum[w] = incl;
    __syncthreads();
    if (w == 0) {
        int s = (lane < 8) ? warpsum[lane] : 0;
        int is = s;
#pragma unroll
        for (int o = 1; o < 8; o <<= 1) {
            int u = __shfl_up_sync(~0u, is, o);
            if (lane >= o) is += u;
        }
        if (lane < 8) warpsum[lane] = is - s;
    }
    __syncthreads();
    return incl + warpsum[w];
}

__global__ void k_scanA() {
    __shared__ int warpsum[8];
    int i = blockIdx.x * 256 + threadIdx.x;
    int v = (i < NN) ? g_cnt[i] : 0;
    int incl = block_incl_scan(v, warpsum);
    if (i < NN) g_off[i + 1] = incl;
    if (threadIdx.x == 255) g_bsum[blockIdx.x] = incl;
}

__global__ void k_scanB() {
    __shared__ int sh[SCANB];
    int t = threadIdx.x;
    if (t < SCANB) sh[t] = g_bsum[t];
    __syncthreads();
    if (t == 0) {
        int run = 0;
        for (int b = 0; b < SCANB; b++) {
            int v = sh[b];
            g_boff[b] = run;
            run += v;
        }
    }
}

__global__ void k_scanC() {
    int i = blockIdx.x * 256 + threadIdx.x;
    if (i == 0) g_off[0] = 0;
    if (i >= NN) return;
    int incl = g_off[i + 1] + g_boff[blockIdx.x];
    g_off[i + 1] = incl;
    g_cur[i] = incl - g_cnt[i];
}

// ---------------- scatter: src index only into CSR order ----------------
__global__ void k_scat() {
    int e = blockIdx.x * blockDim.x + threadIdx.x;
    if (e >= ETOT) return;
    int d = g_dst[e];
    int p = atomicAdd(&g_cur[d], 1);
    g_srco[p] = g_src[e];
}

// ---------------- agg L1: fused logit/exp/softmax + gather, sync-free ----------------
// 256 threads = 4 nodes x 64 threads; thread owns 4 contiguous channels.
__global__ void __launch_bounds__(256) k_agg1() {
    int node = blockIdx.x * 4 + (threadIdx.x >> 6);
    if (node >= NN) return;
    int t = threadIdx.x & 63;
    int head = t >> 4;
    float adv = g_ad1[node * 4 + head];
    int beg = g_off[node], end = g_off[node + 1];
    float4 acc = make_float4(0.f, 0.f, 0.f, 0.f);
    float den = 0.f;
    int i = beg;
    for (; i + 2 <= end; i += 2) {
        int s0 = g_srco[i], s1 = g_srco[i + 1];
        float w0 = __expf(lrelu(g_as1[s0 * 4 + head] + adv));
        float w1 = __expf(lrelu(g_as1[s1 * 4 + head] + adv));
        float4 x0 = *(const float4*)(g_h1 + (size_t)s0 * C1 + t * 4);
        float4 x1 = *(const float4*)(g_h1 + (size_t)s1 * C1 + t * 4);
        acc.x += w0 * x0.x + w1 * x1.x;
        acc.y += w0 * x0.y + w1 * x1.y;
        acc.z += w0 * x0.z + w1 * x1.z;
        acc.w += w0 * x0.w + w1 * x1.w;
        den += w0 + w1;
    }
    for (; i < end; i++) {
        int s0 = g_srco[i];
        float w0 = __expf(lrelu(g_as1[s0 * 4 + head] + adv));
        float4 x0 = *(const float4*)(g_h1 + (size_t)s0 * C1 + t * 4);
        acc.x += w0 * x0.x;
        acc.y += w0 * x0.y;
        acc.z += w0 * x0.z;
        acc.w += w0 * x0.w;
        den += w0;
    }
    float inv = 1.f / (den + 1e-16f);
    *(float4*)(g_b1 + (size_t)node * C1 + t * 4) =
        make_float4(acc.x * inv, acc.y * inv, acc.z * inv, acc.w * inv);
}

// ---------------- agg L2: warp per node, fused softmax ----------------
// 256 threads = 8 nodes x 32 threads; thread owns 4 contiguous channels.
__global__ void __launch_bounds__(256) k_agg2() {
    int node = blockIdx.x * 8 + (threadIdx.x >> 5);
    if (node >= NN) return;
    int t = threadIdx.x & 31;
    float adv = g_ad2[node];
    int beg = g_off[node], end = g_off[node + 1];
    float4 acc = make_float4(0.f, 0.f, 0.f, 0.f);
    float den = 0.f;
    int i = beg;
    for (; i + 2 <= end; i += 2) {
        int s0 = g_srco[i], s1 = g_srco[i + 1];
        float w0 = __expf(lrelu(g_as2[s0] + adv));
        float w1 = __expf(lrelu(g_as2[s1] + adv));
        float4 x0 = *(const float4*)(g_h2 + (size_t)s0 * C2 + t * 4);
        float4 x1 = *(const float4*)(g_h2 + (size_t)s1 * C2 + t * 4);
        acc.x += w0 * x0.x + w1 * x1.x;
        acc.y += w0 * x0.y + w1 * x1.y;
        acc.z += w0 * x0.z + w1 * x1.z;
        acc.w += w0 * x0.w + w1 * x1.w;
        den += w0 + w1;
    }
    for (; i < end; i++) {
        int s0 = g_srco[i];
        float w0 = __expf(lrelu(g_as2[s0] + adv));
        float4 x0 = *(const float4*)(g_h2 + (size_t)s0 * C2 + t * 4);
        acc.x += w0 * x0.x;
        acc.y += w0 * x0.y;
        acc.z += w0 * x0.z;
        acc.w += w0 * x0.w;
        den += w0;
    }
    float inv = 1.f / (den + 1e-16f);
    *(float4*)(g_b2 + (size_t)node * C2 + t * 4) =
        make_float4(acc.x * inv, acc.y * inv, acc.z * inv, acc.w * inv);
}

// ---------------- BatchNorm ----------------
__global__ void k_bnred1() {
    int c = threadIdx.x;
    int rows = (NN + gridDim.x - 1) / gridDim.x;
    int r0 = blockIdx.x * rows, r1 = min(NN, r0 + rows);
    float s = 0.f, q = 0.f;
    for (int r = r0; r < r1; r++) {
        float v = g_b1[(size_t)r * C1 + c];
        s += v;
        q += v * v;
    }
    atomicAdd(&g_sum[c], s);
    atomicAdd(&g_sq[c], q);
}
__global__ void k_bnred2() {
    int c = threadIdx.x;
    int rows = (NN + gridDim.x - 1) / gridDim.x;
    int r0 = blockIdx.x * rows, r1 = min(NN, r0 + rows);
    float s = 0.f, q = 0.f;
    for (int r = r0; r < r1; r++) {
        float v = g_b2[(size_t)r * C2 + c];
        s += v;
        q += v * v;
    }
    atomicAdd(&g_sum[c], s);
    atomicAdd(&g_sq[c], q);
}

__global__ void k_bnapply1(const float* __restrict__ gamma, const float* __restrict__ beta) {
    int i = blockIdx.x * blockDim.x + threadIdx.x;
    if (i >= NN * C1) return;
    int c = i & (C1 - 1);
    float mean = g_sum[c] * (1.f / NN);
    float var = g_sq[c] * (1.f / NN) - mean * mean;
    float v = (g_b1[i] - mean) * rsqrtf(var + BN_EPS) * gamma[c] + beta[c];
    g_b1[i] = v > 0.f ? v : expm1f(v);
}
__global__ void k_bnapply2(float* __restrict__ out, const float* __restrict__ gamma,
                           const float* __restrict__ beta) {
    int i = blockIdx.x * blockDim.x + threadIdx.x;
    if (i >= NN * C2) return;
    int c = i & (C2 - 1);
    float mean = g_sum[c] * (1.f / NN);
    float var = g_sq[c] * (1.f / NN) - mean * mean;
    out[i] = (g_b2[i] - mean) * rsqrtf(var + BN_EPS) * gamma[c] + beta[c];
}

// ---------------- launch ----------------
extern "C" void kernel_launch(void* const* d_in, const int* in_sizes, int n_in,
                              void* d_out, int out_size) {
    const float* x   = (const float*)d_in[0];
    const void*  ei  = d_in[1];
    const float* W1  = (const float*)d_in[2];
    const float* as1 = (const float*)d_in[3];
    const float* ad1 = (const float*)d_in[4];
    const float* gm1 = (const float*)d_in[6];
    const float* bt1 = (const float*)d_in[7];
    const float* W2  = (const float*)d_in[8];
    const float* as2 = (const float*)d_in[9];
    const float* ad2 = (const float*)d_in[10];
    const float* gm2 = (const float*)d_in[12];
    const float* bt2 = (const float*)d_in[13];
    float* out = (float*)d_out;

    const int EB = (ETOT + 255) / 256;

    k_detect<<<1, 1>>>((const unsigned*)ei);

    // layer 1 — NOTE: k_alphas1 zeroes g_cnt, so it must precede k_count
    k_gemm1<<<dim3(C1 / 64, (NN + 127) / 128), 256>>>(x, W1);
    k_alphas1<<<(NN * H1 + 255) / 256, 256>>>(as1, ad1);
    k_count<<<EB, 256>>>(ei);
    k_scanA<<<SCANB, 256>>>();
    k_scanB<<<1, 128>>>();
    k_scanC<<<SCANB, 256>>>();
    k_scat<<<EB, 256>>>();
    k_agg1<<<(NN + 3) / 4, 256>>>();
    k_bnred1<<<148, C1>>>();
    k_bnapply1<<<(NN * C1 + 255) / 256, 256>>>(gm1, bt1);

    // layer 2
    k_gemm2<<<dim3(C2 / 64, (NN + 127) / 128), 256>>>(W2);
    k_alphas2<<<(NN + 255) / 256, 256>>>(as2, ad2);
    k_agg2<<<(NN + 7) / 8, 256>>>();
    k_bnred2<<<148, C2>>>();
    k_bnapply2<<<(NN * C2 + 255) / 256, 256>>>(out, gm2, bt2);
}